// round 1
// baseline (speedup 1.0000x reference)
#include <cuda_runtime.h>
#include <math.h>

// Problem constants
#define B_  256
#define T_  128
#define X_  256
#define H_  1024
#define NL  3

// Scratch: Euler state y [B, X] and ping-pong pre-activations [B, H]
__device__ float g_y [B_ * X_];
__device__ float g_h0[B_ * H_];
__device__ float g_h1[B_ * H_];

__device__ __forceinline__ const float* sel_src(int s) {
    return (s == 0) ? g_y : (s == 1) ? g_h0 : g_h1;
}
__device__ __forceinline__ float* sel_dst(int s) {
    return (s == 1) ? g_h0 : g_h1;
}

// Init: y = x, out[:, 0, :] = x
__global__ void node_init_kernel(const float* __restrict__ x, float* __restrict__ out) {
    int i = blockIdx.x * blockDim.x + threadIdx.x;   // 0 .. B_*X_-1
    float v = x[i];
    g_y[i] = v;
    int b = i / X_;
    int c = i % X_;
    out[(size_t)b * T_ * X_ + 0 * X_ + c] = v;
}

// GEMM: C[M=256, N] = act(A[256, K]) @ W[K, N] + bias[N]
//   TANH_A: apply tanh to A elements while staging into SMEM
//   MODE 0: store pre-activation result into sel_dst(csel)
//   MODE 1: f = result; y = g_y + dt * f; g_y = y; out[b, t+1, n] = y
// Block tile: BM=32, BN=64, BK=32; 256 threads; per-thread 2x4 outputs.
template <bool TANH_A, int MODE>
__global__ void node_gemm_kernel(int asel,
                                 const float* __restrict__ W,
                                 const float* __restrict__ bias,
                                 int csel,
                                 int N, int K,
                                 float* __restrict__ out,
                                 const float* __restrict__ ts,
                                 int t)
{
    constexpr int BM = 32, BN = 64, BK = 32;
    __shared__ float As[BK][BM + 1];   // transposed A tile, +1 pad (conflict-free STS)
    __shared__ float Ws[BK][BN];       // W tile

    const float* __restrict__ A = sel_src(asel);

    const int tid = threadIdx.x;              // 0..255
    const int bm  = blockIdx.y * BM;
    const int bn  = blockIdx.x * BN;

    const int tx = tid & 15;                  // 16 col groups (4 cols each)
    const int ty = tid >> 4;                  // 16 row groups (2 rows each)

    float acc[2][4] = {{0.f,0.f,0.f,0.f},{0.f,0.f,0.f,0.f}};

    for (int k0 = 0; k0 < K; k0 += BK) {
        // ---- Stage A tile (32x32): 256 float4 slots, one per thread ----
        {
            int row  = tid >> 3;              // 0..31
            int col4 = tid & 7;               // 0..7 (x4 floats)
            float4 v = *reinterpret_cast<const float4*>(&A[(bm + row) * K + k0 + col4 * 4]);
            if (TANH_A) {
                v.x = tanhf(v.x); v.y = tanhf(v.y);
                v.z = tanhf(v.z); v.w = tanhf(v.w);
            }
            As[col4 * 4 + 0][row] = v.x;
            As[col4 * 4 + 1][row] = v.y;
            As[col4 * 4 + 2][row] = v.z;
            As[col4 * 4 + 3][row] = v.w;
        }
        // ---- Stage W tile (32x64): 512 float4 slots, two per thread ----
        #pragma unroll
        for (int i = 0; i < 2; i++) {
            int idx  = tid + i * 256;         // 0..511
            int row  = idx >> 4;              // 0..31
            int col4 = idx & 15;              // 0..15 (x4 floats)
            float4 v = *reinterpret_cast<const float4*>(&W[(size_t)(k0 + row) * N + bn + col4 * 4]);
            *reinterpret_cast<float4*>(&Ws[row][col4 * 4]) = v;
        }
        __syncthreads();

        // ---- Compute ----
        #pragma unroll
        for (int k = 0; k < BK; k++) {
            float a0 = As[k][ty * 2 + 0];
            float a1 = As[k][ty * 2 + 1];
            float4 w = *reinterpret_cast<const float4*>(&Ws[k][tx * 4]);
            acc[0][0] += a0 * w.x; acc[0][1] += a0 * w.y;
            acc[0][2] += a0 * w.z; acc[0][3] += a0 * w.w;
            acc[1][0] += a1 * w.x; acc[1][1] += a1 * w.y;
            acc[1][2] += a1 * w.z; acc[1][3] += a1 * w.w;
        }
        __syncthreads();
    }

    const int m0 = bm + ty * 2;
    const int n0 = bn + tx * 4;

    if (MODE == 0) {
        float* __restrict__ C = sel_dst(csel);
        #pragma unroll
        for (int i = 0; i < 2; i++) {
            #pragma unroll
            for (int j = 0; j < 4; j++) {
                C[(m0 + i) * N + n0 + j] = acc[i][j] + bias[n0 + j];
            }
        }
    } else {
        // Final layer: N == X_. Euler update + output store.
        float dt = ts[t + 1] - ts[t];
        #pragma unroll
        for (int i = 0; i < 2; i++) {
            #pragma unroll
            for (int j = 0; j < 4; j++) {
                float f = acc[i][j] + bias[n0 + j];
                int   yi = (m0 + i) * X_ + (n0 + j);
                float y  = g_y[yi] + dt * f;
                g_y[yi]  = y;
                out[(size_t)(m0 + i) * T_ * X_ + (size_t)(t + 1) * X_ + (n0 + j)] = y;
            }
        }
    }
}

extern "C" void kernel_launch(void* const* d_in, const int* in_sizes, int n_in,
                              void* d_out, int out_size)
{
    const float* x     = (const float*)d_in[0];   // [B, 1, X]
    const float* ts    = (const float*)d_in[1];   // [T]
    const float* W_in  = (const float*)d_in[2];   // [X, H]
    const float* b_in  = (const float*)d_in[3];   // [H]
    const float* W_h   = (const float*)d_in[4];   // [NL, H, H]
    const float* b_h   = (const float*)d_in[5];   // [NL, H]
    const float* W_out = (const float*)d_in[6];   // [H, X]
    const float* b_out = (const float*)d_in[7];   // [X]
    float* out = (float*)d_out;                   // [B, T, X]

    // y = x; out[:,0,:] = x
    node_init_kernel<<<(B_ * X_) / 256, 256>>>(x, out);

    dim3 blk(256);
    dim3 gridH(H_ / 64, B_ / 32);   // (16, 8) = 128 blocks for N=1024
    dim3 gridO(X_ / 64, B_ / 32);   // (4, 8)  =  32 blocks for N=256

    for (int t = 0; t < T_ - 1; t++) {
        // h0 = y @ W_in + b_in            (no tanh on y)
        node_gemm_kernel<false, 0><<<gridH, blk>>>(0, W_in, b_in, 1, H_, X_, nullptr, nullptr, 0);
        // a1 = tanh(h0) @ W_h[0] + b_h[0]
        node_gemm_kernel<true, 0><<<gridH, blk>>>(1, W_h + 0 * H_ * H_, b_h + 0 * H_, 2, H_, H_, nullptr, nullptr, 0);
        // a2 = tanh(a1) @ W_h[1] + b_h[1]
        node_gemm_kernel<true, 0><<<gridH, blk>>>(2, W_h + 1 * H_ * H_, b_h + 1 * H_, 1, H_, H_, nullptr, nullptr, 0);
        // a3 = tanh(a2) @ W_h[2] + b_h[2]
        node_gemm_kernel<true, 0><<<gridH, blk>>>(1, W_h + 2 * H_ * H_, b_h + 2 * H_, 2, H_, H_, nullptr, nullptr, 0);
        // f = tanh(a3) @ W_out + b_out; y += dt*f; out[:, t+1, :] = y
        node_gemm_kernel<true, 1><<<gridO, blk>>>(2, W_out, b_out, 0, X_, H_, out, ts, t);
    }
}

// round 3
// speedup vs baseline: 1.0688x; 1.0688x over previous
#include <cuda_runtime.h>
#include <cstdint>
#include <math.h>
#include <mma.h>

using namespace nvcuda;

#define B_  256
#define T_  128
#define X_  256
#define H_  1024

#define BM 128
#define BN 64
#define BK 32
#define ALD 36                 // A smem leading dim (floats)
#define BLD 68                 // B smem leading dim (floats)
#define A_TILE (BM * ALD)      // 4608 floats
#define B_TILE (BK * BLD)      // 2176 floats
#define DYN_SMEM ((2 * A_TILE + 2 * B_TILE) * 4)   // 54272 bytes

// ---------------- device scratch ----------------
__device__ float g_y  [B_ * X_];   // fp32 Euler state
__device__ float g_yr [B_ * X_];   // tf32-rounded copy (GEMM A operand)
__device__ float g_h0 [B_ * H_];   // rounded tanh activations (ping)
__device__ float g_h1 [B_ * H_];   // (pong)
// tf32-rounded weights, layout unchanged [K, N]
#define WR_IN_OFF  0
#define WR_H_OFF   (X_ * H_)
#define WR_OUT_OFF (X_ * H_ + 3 * H_ * H_)
__device__ float g_wr [X_ * H_ + 3 * H_ * H_ + H_ * X_];

__device__ __forceinline__ float f2tf32r(float x) {
    uint32_t u;
    asm("cvt.rna.tf32.f32 %0, %1;" : "=r"(u) : "f"(x));
    return __uint_as_float(u);
}

#define CP16(dst, src) \
    asm volatile("cp.async.cg.shared.global [%0], [%1], 16;" :: "r"(dst), "l"(src))

// ---------------- init / weight rounding ----------------
__global__ void node_init_kernel(const float* __restrict__ x, float* __restrict__ out) {
    int i = blockIdx.x * blockDim.x + threadIdx.x;
    float v = x[i];
    g_y[i]  = v;
    g_yr[i] = f2tf32r(v);
    int b = i / X_, c = i % X_;
    out[(size_t)b * T_ * X_ + c] = v;
}

__global__ void round_kernel(const float* __restrict__ src, float* __restrict__ dst, int n) {
    int i = blockIdx.x * blockDim.x + threadIdx.x;
    if (i < n) dst[i] = f2tf32r(src[i]);
}

// ---------------- WMMA tf32 GEMM ----------------
// C[M=256, N] = A[256, K] @ W[K, N] (+bias, +epilogue)
// MODE 0: Cout = tf32round(tanh(z + bias))
// MODE 1: f = z + bias; y += dt*f; g_y/g_yr updated; out[:, t+1, :] = y
template <int MODE>
__global__ void __launch_bounds__(256, 1) gemm_wmma(
    const float* __restrict__ A, const float* __restrict__ W,
    const float* __restrict__ bias, float* __restrict__ Cout,
    int K, int N,
    float* __restrict__ gy, float* __restrict__ gyr,
    float* __restrict__ out, const float* __restrict__ ts, int t)
{
    extern __shared__ float smem[];
    float* As = smem;                 // [2][A_TILE]
    float* Bs = smem + 2 * A_TILE;    // [2][B_TILE]

    const int tid = threadIdx.x;
    const int bm  = blockIdx.y * BM;
    const int bn  = blockIdx.x * BN;
    const int w   = tid >> 5;
    const int wm  = w & 3;            // warp row (4)
    const int wn  = w >> 2;           // warp col (2)

    wmma::fragment<wmma::accumulator, 16, 16, 8, float> c[2][2];
    #pragma unroll
    for (int i = 0; i < 2; i++)
        #pragma unroll
        for (int j = 0; j < 2; j++)
            wmma::fill_fragment(c[i][j], 0.0f);

    const int NIT = K / BK;

    auto loadStage = [&](int it, int buf) {
        const int k0 = it * BK;
        uint32_t asb = (uint32_t)__cvta_generic_to_shared(As + buf * A_TILE);
        #pragma unroll
        for (int i = 0; i < 4; i++) {
            int id = tid + i * 256;                // 0..1023
            int r = id >> 3, c4 = id & 7;
            CP16(asb + (uint32_t)(r * ALD + c4 * 4) * 4,
                 A + (size_t)(bm + r) * K + k0 + c4 * 4);
        }
        uint32_t bsb = (uint32_t)__cvta_generic_to_shared(Bs + buf * B_TILE);
        #pragma unroll
        for (int i = 0; i < 2; i++) {
            int id = tid + i * 256;                // 0..511
            int r = id >> 4, c4 = id & 15;
            CP16(bsb + (uint32_t)(r * BLD + c4 * 4) * 4,
                 W + (size_t)(k0 + r) * N + bn + c4 * 4);
        }
        asm volatile("cp.async.commit_group;" ::: "memory");
    };

    loadStage(0, 0);

    for (int it = 0; it < NIT; it++) {
        asm volatile("cp.async.wait_group 0;" ::: "memory");
        __syncthreads();
        if (it + 1 < NIT) loadStage(it + 1, (it + 1) & 1);

        const float* Ab = As + (it & 1) * A_TILE;
        const float* Bb = Bs + (it & 1) * B_TILE;

        #pragma unroll
        for (int kf = 0; kf < 4; kf++) {
            wmma::fragment<wmma::matrix_a, 16, 16, 8, wmma::precision::tf32, wmma::row_major> a0, a1;
            wmma::fragment<wmma::matrix_b, 16, 16, 8, wmma::precision::tf32, wmma::row_major> b0, b1;
            wmma::load_matrix_sync(a0, Ab + (wm * 32 +  0) * ALD + kf * 8, ALD);
            wmma::load_matrix_sync(a1, Ab + (wm * 32 + 16) * ALD + kf * 8, ALD);
            wmma::load_matrix_sync(b0, Bb + (kf * 8) * BLD + wn * 32 +  0, BLD);
            wmma::load_matrix_sync(b1, Bb + (kf * 8) * BLD + wn * 32 + 16, BLD);
            wmma::mma_sync(c[0][0], a0, b0, c[0][0]);
            wmma::mma_sync(c[0][1], a0, b1, c[0][1]);
            wmma::mma_sync(c[1][0], a1, b0, c[1][0]);
            wmma::mma_sync(c[1][1], a1, b1, c[1][1]);
        }
    }

    // ---- epilogue: dump accumulators to smem, then elementwise ----
    __syncthreads();
    float* E = smem;   // [BM][BLD], 34816 B — reuses tile buffers
    #pragma unroll
    for (int i = 0; i < 2; i++)
        #pragma unroll
        for (int j = 0; j < 2; j++)
            wmma::store_matrix_sync(E + (size_t)(wm * 32 + i * 16) * BLD + wn * 32 + j * 16,
                                    c[i][j], BLD, wmma::mem_row_major);
    __syncthreads();

    const int r     = tid >> 1;            // 0..127
    const int cbase = (tid & 1) * 32;      // 0 or 32

    if (MODE == 0) {
        #pragma unroll
        for (int j = 0; j < 8; j++) {
            int col = cbase + j * 4;
            float4 v = *reinterpret_cast<float4*>(&E[r * BLD + col]);
            v.x = f2tf32r(tanhf(v.x + bias[bn + col + 0]));
            v.y = f2tf32r(tanhf(v.y + bias[bn + col + 1]));
            v.z = f2tf32r(tanhf(v.z + bias[bn + col + 2]));
            v.w = f2tf32r(tanhf(v.w + bias[bn + col + 3]));
            *reinterpret_cast<float4*>(&Cout[(size_t)(bm + r) * N + bn + col]) = v;
        }
    } else {
        const float dt = ts[t + 1] - ts[t];
        #pragma unroll
        for (int j = 0; j < 8; j++) {
            int col = cbase + j * 4;
            int idx = (bm + r) * X_ + bn + col;
            float4 yv = *reinterpret_cast<float4*>(&gy[idx]);
            yv.x += dt * (E[r * BLD + col + 0] + bias[bn + col + 0]);
            yv.y += dt * (E[r * BLD + col + 1] + bias[bn + col + 1]);
            yv.z += dt * (E[r * BLD + col + 2] + bias[bn + col + 2]);
            yv.w += dt * (E[r * BLD + col + 3] + bias[bn + col + 3]);
            *reinterpret_cast<float4*>(&gy[idx]) = yv;
            float4 yr;
            yr.x = f2tf32r(yv.x); yr.y = f2tf32r(yv.y);
            yr.z = f2tf32r(yv.z); yr.w = f2tf32r(yv.w);
            *reinterpret_cast<float4*>(&gyr[idx]) = yr;
            *reinterpret_cast<float4*>(&out[(size_t)(bm + r) * T_ * X_ +
                                            (size_t)(t + 1) * X_ + bn + col]) = yv;
        }
    }
}

// ---------------- host ----------------
extern "C" void kernel_launch(void* const* d_in, const int* in_sizes, int n_in,
                              void* d_out, int out_size)
{
    const float* x     = (const float*)d_in[0];
    const float* ts    = (const float*)d_in[1];
    const float* W_in  = (const float*)d_in[2];
    const float* b_in  = (const float*)d_in[3];
    const float* W_h   = (const float*)d_in[4];
    const float* b_h   = (const float*)d_in[5];
    const float* W_out = (const float*)d_in[6];
    const float* b_out = (const float*)d_in[7];
    float* out = (float*)d_out;

    float *py, *pyr, *ph0, *ph1, *pwr;
    cudaGetSymbolAddress((void**)&py,  g_y);
    cudaGetSymbolAddress((void**)&pyr, g_yr);
    cudaGetSymbolAddress((void**)&ph0, g_h0);
    cudaGetSymbolAddress((void**)&ph1, g_h1);
    cudaGetSymbolAddress((void**)&pwr, g_wr);

    static bool attr_set = false;
    if (!attr_set) {
        cudaFuncSetAttribute(gemm_wmma<0>, cudaFuncAttributeMaxDynamicSharedMemorySize, DYN_SMEM);
        cudaFuncSetAttribute(gemm_wmma<1>, cudaFuncAttributeMaxDynamicSharedMemorySize, DYN_SMEM);
        attr_set = true;
    }

    // tf32-round all weights (layout preserved)
    round_kernel<<<(X_ * H_ + 255) / 256, 256>>>(W_in,  pwr + WR_IN_OFF,  X_ * H_);
    round_kernel<<<(3 * H_ * H_ + 255) / 256, 256>>>(W_h, pwr + WR_H_OFF, 3 * H_ * H_);
    round_kernel<<<(H_ * X_ + 255) / 256, 256>>>(W_out, pwr + WR_OUT_OFF, H_ * X_);

    node_init_kernel<<<(B_ * X_) / 256, 256>>>(x, out);

    dim3 blk(256);
    dim3 gridH(H_ / BN, B_ / BM);   // (16, 2)
    dim3 gridO(X_ / BN, B_ / BM);   // (4, 2)

    const float* Wr_in  = pwr + WR_IN_OFF;
    const float* Wr_h   = pwr + WR_H_OFF;
    const float* Wr_out = pwr + WR_OUT_OFF;

    for (int t = 0; t < T_ - 1; t++) {
        gemm_wmma<0><<<gridH, blk, DYN_SMEM>>>(pyr, Wr_in,            b_in,       ph0, X_, H_, nullptr, nullptr, nullptr, nullptr, 0);
        gemm_wmma<0><<<gridH, blk, DYN_SMEM>>>(ph0, Wr_h + 0*H_*H_,   b_h + 0*H_, ph1, H_, H_, nullptr, nullptr, nullptr, nullptr, 0);
        gemm_wmma<0><<<gridH, blk, DYN_SMEM>>>(ph1, Wr_h + 1*H_*H_,   b_h + 1*H_, ph0, H_, H_, nullptr, nullptr, nullptr, nullptr, 0);
        gemm_wmma<0><<<gridH, blk, DYN_SMEM>>>(ph0, Wr_h + 2*H_*H_,   b_h + 2*H_, ph1, H_, H_, nullptr, nullptr, nullptr, nullptr, 0);
        gemm_wmma<1><<<gridO, blk, DYN_SMEM>>>(ph1, Wr_out,           b_out, nullptr, H_, X_, py, pyr, out, ts, t);
    }
}

// round 4
// speedup vs baseline: 1.8968x; 1.7747x over previous
#include <cuda_runtime.h>
#include <cstdint>
#include <math.h>
#include <mma.h>

using namespace nvcuda;

#define B_  256
#define T_  128
#define X_  256
#define H_  1024

#define BM 64
#define BN 64
#define BK 32
#define STAGES 4
#define ALD 40                    // A smem row stride (floats): 32 + 8 pad
#define BLD 72                    // B smem row stride (floats): 64 + 8 pad
#define A_ST (BM * ALD)           // 2560 floats
#define B_ST (BK * BLD)           // 2304 floats
#define STAGE_FLOATS (A_ST + B_ST)
#define DYN_SMEM (STAGES * STAGE_FLOATS * 4)   // 77824 bytes

// ---------------- device scratch ----------------
__device__ float g_y  [B_ * X_];   // fp32 Euler state
__device__ float g_yr [B_ * X_];   // tf32-rounded copy (GEMM A operand)
__device__ float g_h0 [B_ * H_];
__device__ float g_h1 [B_ * H_];
#define WR_IN_OFF  0
#define WR_H_OFF   (X_ * H_)
#define WR_OUT_OFF (X_ * H_ + 3 * H_ * H_)
__device__ float g_wr [X_ * H_ + 3 * H_ * H_ + H_ * X_];

__device__ __forceinline__ float f2tf32r(float x) {
    uint32_t u;
    asm("cvt.rna.tf32.f32 %0, %1;" : "=r"(u) : "f"(x));
    return __uint_as_float(u);
}

#define CP16(dst, src) \
    asm volatile("cp.async.cg.shared.global [%0], [%1], 16;" :: "r"(dst), "l"(src))
#define CP_COMMIT() asm volatile("cp.async.commit_group;" ::: "memory")
#define CP_WAIT2()  asm volatile("cp.async.wait_group 2;" ::: "memory")

// ---------------- init / weight rounding ----------------
__global__ void node_init_kernel(const float* __restrict__ x, float* __restrict__ out) {
    int i = blockIdx.x * blockDim.x + threadIdx.x;
    float v = x[i];
    g_y[i]  = v;
    g_yr[i] = f2tf32r(v);
    int b = i / X_, c = i % X_;
    out[(size_t)b * T_ * X_ + c] = v;
}

__global__ void round_kernel(const float* __restrict__ src, float* __restrict__ dst, int n) {
    int i = blockIdx.x * blockDim.x + threadIdx.x;
    if (i < n) dst[i] = f2tf32r(src[i]);
}

// ---------------- WMMA tf32 GEMM, 4-stage cp.async pipeline ----------------
// C[256, N] = A[256, K] @ W[K, N] (+bias, +epilogue)
// MODE 0: Cout = tf32round(tanh(z + bias))
// MODE 1: f = z + bias; y += dt*f; update g_y/g_yr; out[:, t+1, :] = y
template <int MODE>
__global__ void __launch_bounds__(128, 1) gemm_wmma(
    const float* __restrict__ A, const float* __restrict__ W,
    const float* __restrict__ bias, float* __restrict__ Cout,
    int K, int N,
    float* __restrict__ gy, float* __restrict__ gyr,
    float* __restrict__ out, const float* __restrict__ ts, int t)
{
    extern __shared__ float smem[];

    const int tid = threadIdx.x;          // 0..127
    const int bm  = blockIdx.y * BM;
    const int bn  = blockIdx.x * BN;
    const int w   = tid >> 5;             // 0..3
    const int wm  = w & 1;                // warp row
    const int wn  = w >> 1;               // warp col

    wmma::fragment<wmma::accumulator, 16, 16, 8, float> c[2][2];
    #pragma unroll
    for (int i = 0; i < 2; i++)
        #pragma unroll
        for (int j = 0; j < 2; j++)
            wmma::fill_fragment(c[i][j], 0.0f);

    const int NIT = K / BK;

    auto loadStage = [&](int it) {
        if (it < NIT) {
            const int k0  = it * BK;
            float* As = smem + (it % STAGES) * STAGE_FLOATS;
            float* Bs = As + A_ST;
            uint32_t asb = (uint32_t)__cvta_generic_to_shared(As);
            uint32_t bsb = (uint32_t)__cvta_generic_to_shared(Bs);
            #pragma unroll
            for (int i = 0; i < 4; i++) {           // A: 512 float4
                int id = tid + i * 128;
                int r = id >> 3, c4 = id & 7;
                CP16(asb + (uint32_t)(r * ALD + c4 * 4) * 4,
                     A + (size_t)(bm + r) * K + k0 + c4 * 4);
            }
            #pragma unroll
            for (int i = 0; i < 4; i++) {           // B: 512 float4
                int id = tid + i * 128;
                int r = id >> 4, c4 = id & 15;
                CP16(bsb + (uint32_t)(r * BLD + c4 * 4) * 4,
                     W + (size_t)(k0 + r) * N + bn + c4 * 4);
            }
        }
        CP_COMMIT();   // commit unconditionally to keep group accounting uniform
    };

    loadStage(0); loadStage(1); loadStage(2);

    for (int it = 0; it < NIT; it++) {
        CP_WAIT2();              // ≤2 groups pending -> stage `it` landed
        __syncthreads();

        const float* Ab = smem + (it % STAGES) * STAGE_FLOATS;
        const float* Bb = Ab + A_ST;

        #pragma unroll
        for (int kf = 0; kf < BK / 8; kf++) {
            wmma::fragment<wmma::matrix_a, 16, 16, 8, wmma::precision::tf32, wmma::row_major> a0, a1;
            wmma::fragment<wmma::matrix_b, 16, 16, 8, wmma::precision::tf32, wmma::row_major> b0, b1;
            wmma::load_matrix_sync(a0, Ab + (wm * 32 +  0) * ALD + kf * 8, ALD);
            wmma::load_matrix_sync(a1, Ab + (wm * 32 + 16) * ALD + kf * 8, ALD);
            wmma::load_matrix_sync(b0, Bb + (kf * 8) * BLD + wn * 32 +  0, BLD);
            wmma::load_matrix_sync(b1, Bb + (kf * 8) * BLD + wn * 32 + 16, BLD);
            wmma::mma_sync(c[0][0], a0, b0, c[0][0]);
            wmma::mma_sync(c[0][1], a0, b1, c[0][1]);
            wmma::mma_sync(c[1][0], a1, b0, c[1][0]);
            wmma::mma_sync(c[1][1], a1, b1, c[1][1]);
        }
        loadStage(it + 3);
    }

    // ---- epilogue: accumulators -> smem -> elementwise ----
    __syncthreads();
    float* E = smem;   // [BM][BLD] = 64*72 floats, fits in tile space
    #pragma unroll
    for (int i = 0; i < 2; i++)
        #pragma unroll
        for (int j = 0; j < 2; j++)
            wmma::store_matrix_sync(E + (size_t)(wm * 32 + i * 16) * BLD + wn * 32 + j * 16,
                                    c[i][j], BLD, wmma::mem_row_major);
    __syncthreads();

    const int r     = tid >> 1;           // 0..63
    const int cbase = (tid & 1) * 32;     // 0 / 32

    if (MODE == 0) {
        #pragma unroll
        for (int j = 0; j < 8; j++) {
            int col = cbase + j * 4;
            float4 v = *reinterpret_cast<float4*>(&E[r * BLD + col]);
            v.x = f2tf32r(tanhf(v.x + bias[bn + col + 0]));
            v.y = f2tf32r(tanhf(v.y + bias[bn + col + 1]));
            v.z = f2tf32r(tanhf(v.z + bias[bn + col + 2]));
            v.w = f2tf32r(tanhf(v.w + bias[bn + col + 3]));
            *reinterpret_cast<float4*>(&Cout[(size_t)(bm + r) * N + bn + col]) = v;
        }
    } else {
        const float dt = ts[t + 1] - ts[t];
        #pragma unroll
        for (int j = 0; j < 8; j++) {
            int col = cbase + j * 4;
            int idx = (bm + r) * X_ + bn + col;
            float4 yv = *reinterpret_cast<float4*>(&gy[idx]);
            yv.x += dt * (E[r * BLD + col + 0] + bias[bn + col + 0]);
            yv.y += dt * (E[r * BLD + col + 1] + bias[bn + col + 1]);
            yv.z += dt * (E[r * BLD + col + 2] + bias[bn + col + 2]);
            yv.w += dt * (E[r * BLD + col + 3] + bias[bn + col + 3]);
            *reinterpret_cast<float4*>(&gy[idx]) = yv;
            float4 yr;
            yr.x = f2tf32r(yv.x); yr.y = f2tf32r(yv.y);
            yr.z = f2tf32r(yv.z); yr.w = f2tf32r(yv.w);
            *reinterpret_cast<float4*>(&gyr[idx]) = yr;
            *reinterpret_cast<float4*>(&out[(size_t)(bm + r) * T_ * X_ +
                                            (size_t)(t + 1) * X_ + bn + col]) = yv;
        }
    }
}

// ---------------- host ----------------
extern "C" void kernel_launch(void* const* d_in, const int* in_sizes, int n_in,
                              void* d_out, int out_size)
{
    const float* x     = (const float*)d_in[0];
    const float* ts    = (const float*)d_in[1];
    const float* W_in  = (const float*)d_in[2];
    const float* b_in  = (const float*)d_in[3];
    const float* W_h   = (const float*)d_in[4];
    const float* b_h   = (const float*)d_in[5];
    const float* W_out = (const float*)d_in[6];
    const float* b_out = (const float*)d_in[7];
    float* out = (float*)d_out;

    float *py, *pyr, *ph0, *ph1, *pwr;
    cudaGetSymbolAddress((void**)&py,  g_y);
    cudaGetSymbolAddress((void**)&pyr, g_yr);
    cudaGetSymbolAddress((void**)&ph0, g_h0);
    cudaGetSymbolAddress((void**)&ph1, g_h1);
    cudaGetSymbolAddress((void**)&pwr, g_wr);

    cudaFuncSetAttribute(gemm_wmma<0>, cudaFuncAttributeMaxDynamicSharedMemorySize, DYN_SMEM);
    cudaFuncSetAttribute(gemm_wmma<1>, cudaFuncAttributeMaxDynamicSharedMemorySize, DYN_SMEM);

    round_kernel<<<(X_ * H_ + 255) / 256, 256>>>(W_in,  pwr + WR_IN_OFF,  X_ * H_);
    round_kernel<<<(3 * H_ * H_ + 255) / 256, 256>>>(W_h, pwr + WR_H_OFF, 3 * H_ * H_);
    round_kernel<<<(H_ * X_ + 255) / 256, 256>>>(W_out, pwr + WR_OUT_OFF, H_ * X_);

    node_init_kernel<<<(B_ * X_) / 256, 256>>>(x, out);

    dim3 blk(128);
    dim3 gridH(H_ / BN, B_ / BM);   // (16, 4) = 64 CTAs
    dim3 gridO(X_ / BN, B_ / BM);   // (4, 4)  = 16 CTAs

    const float* Wr_in  = pwr + WR_IN_OFF;
    const float* Wr_h   = pwr + WR_H_OFF;
    const float* Wr_out = pwr + WR_OUT_OFF;

    for (int t = 0; t < T_ - 1; t++) {
        gemm_wmma<0><<<gridH, blk, DYN_SMEM>>>(pyr, Wr_in,          b_in,       ph0, X_, H_, nullptr, nullptr, nullptr, nullptr, 0);
        gemm_wmma<0><<<gridH, blk, DYN_SMEM>>>(ph0, Wr_h + 0*H_*H_, b_h + 0*H_, ph1, H_, H_, nullptr, nullptr, nullptr, nullptr, 0);
        gemm_wmma<0><<<gridH, blk, DYN_SMEM>>>(ph1, Wr_h + 1*H_*H_, b_h + 1*H_, ph0, H_, H_, nullptr, nullptr, nullptr, nullptr, 0);
        gemm_wmma<0><<<gridH, blk, DYN_SMEM>>>(ph0, Wr_h + 2*H_*H_, b_h + 2*H_, ph1, H_, H_, nullptr, nullptr, nullptr, nullptr, 0);
        gemm_wmma<1><<<gridO, blk, DYN_SMEM>>>(ph1, Wr_out,         b_out, nullptr, H_, X_, py, pyr, out, ts, t);
    }
}

// round 5
// speedup vs baseline: 4.4703x; 2.3568x over previous
#include <cuda_runtime.h>
#include <cuda_fp16.h>
#include <cstdint>
#include <math.h>
#include <mma.h>

using namespace nvcuda;

#define B_  256
#define T_  128
#define X_  256
#define H_  1024

#define BM 64
#define BN 64
#define BK 32
#define STAGES 4
#define ALD 40                    // A smem row stride (halves): 32 + 8 pad
#define BLD 72                    // B smem row stride (halves): 64 + 8 pad
#define A_ST (BM * ALD)           // 2560 halves
#define B_ST (BK * BLD)           // 2304 halves
#define STAGE_HALVES (A_ST + B_ST)
#define DYN_SMEM (STAGES * STAGE_HALVES * 2)   // 38912 bytes (epilogue needs 64*72*4=18432 -> ok)

// ---------------- device scratch ----------------
__device__ float  g_y  [B_ * X_];   // fp32 Euler state
__device__ __half g_yh [B_ * X_];   // fp16 copy (GEMM A operand)
__device__ __half g_h0 [B_ * H_];   // fp16 tanh activations (ping)
__device__ __half g_h1 [B_ * H_];   // (pong)
#define WH_IN_OFF  0
#define WH_H_OFF   (X_ * H_)
#define WH_OUT_OFF (X_ * H_ + 3 * H_ * H_)
__device__ __half g_wh [X_ * H_ + 3 * H_ * H_ + H_ * X_];

#define CP16(dst, src) \
    asm volatile("cp.async.cg.shared.global [%0], [%1], 16;" :: "r"(dst), "l"(src))
#define CP_COMMIT() asm volatile("cp.async.commit_group;" ::: "memory")
#define CP_WAIT2()  asm volatile("cp.async.wait_group 2;" ::: "memory")

// ---------------- init / weight conversion ----------------
__global__ void node_init_kernel(const float* __restrict__ x, float* __restrict__ out) {
    int i = blockIdx.x * blockDim.x + threadIdx.x;
    float v = x[i];
    g_y[i]  = v;
    g_yh[i] = __float2half_rn(v);
    int b = i / X_, c = i % X_;
    out[(size_t)b * T_ * X_ + c] = v;
}

__global__ void cvt_kernel(const float* __restrict__ src, __half* __restrict__ dst, int n) {
    int i = blockIdx.x * blockDim.x + threadIdx.x;
    if (i < n) dst[i] = __float2half_rn(src[i]);
}

// ---------------- WMMA fp16 GEMM, fp32 accum, 4-stage cp.async ----------------
// C[256, N] = A[256, K] @ W[K, N] (+bias, +epilogue)
// MODE 0: Cout(half) = tanh(z + bias)
// MODE 1: f = z + bias; y += dt*f; update g_y/g_yh; out[:, t+1, :] = y
template <int MODE>
__global__ void __launch_bounds__(128, 1) gemm_wmma(
    const __half* __restrict__ A, const __half* __restrict__ W,
    const float* __restrict__ bias, __half* __restrict__ Cout,
    int K, int N,
    float* __restrict__ gy, __half* __restrict__ gyh,
    float* __restrict__ out, const float* __restrict__ ts, int t)
{
    extern __shared__ __half smem[];

    const int tid = threadIdx.x;          // 0..127
    const int bm  = blockIdx.y * BM;
    const int bn  = blockIdx.x * BN;
    const int w   = tid >> 5;             // 0..3
    const int wm  = w & 1;
    const int wn  = w >> 1;

    wmma::fragment<wmma::accumulator, 16, 16, 16, float> c[2][2];
    #pragma unroll
    for (int i = 0; i < 2; i++)
        #pragma unroll
        for (int j = 0; j < 2; j++)
            wmma::fill_fragment(c[i][j], 0.0f);

    const int NIT = K / BK;

    auto loadStage = [&](int it) {
        if (it < NIT) {
            const int k0 = it * BK;
            __half* As = smem + (it % STAGES) * STAGE_HALVES;
            __half* Bs = As + A_ST;
            uint32_t asb = (uint32_t)__cvta_generic_to_shared(As);
            uint32_t bsb = (uint32_t)__cvta_generic_to_shared(Bs);
            #pragma unroll
            for (int i = 0; i < 2; i++) {           // A: 256 x 16B (64 rows x 32 halves)
                int id = tid + i * 128;
                int r = id >> 2, c8 = id & 3;       // 4 chunks of 8 halves per row
                CP16(asb + (uint32_t)(r * ALD + c8 * 8) * 2,
                     A + (size_t)(bm + r) * K + k0 + c8 * 8);
            }
            #pragma unroll
            for (int i = 0; i < 2; i++) {           // B: 256 x 16B (32 rows x 64 halves)
                int id = tid + i * 128;
                int r = id >> 3, c8 = id & 7;
                CP16(bsb + (uint32_t)(r * BLD + c8 * 8) * 2,
                     W + (size_t)(k0 + r) * N + bn + c8 * 8);
            }
        }
        CP_COMMIT();
    };

    loadStage(0); loadStage(1); loadStage(2);

    for (int it = 0; it < NIT; it++) {
        CP_WAIT2();
        __syncthreads();

        const __half* Ab = smem + (it % STAGES) * STAGE_HALVES;
        const __half* Bb = Ab + A_ST;

        #pragma unroll
        for (int kf = 0; kf < BK / 16; kf++) {
            wmma::fragment<wmma::matrix_a, 16, 16, 16, __half, wmma::row_major> a0, a1;
            wmma::fragment<wmma::matrix_b, 16, 16, 16, __half, wmma::row_major> b0, b1;
            wmma::load_matrix_sync(a0, Ab + (wm * 32 +  0) * ALD + kf * 16, ALD);
            wmma::load_matrix_sync(a1, Ab + (wm * 32 + 16) * ALD + kf * 16, ALD);
            wmma::load_matrix_sync(b0, Bb + (kf * 16) * BLD + wn * 32 +  0, BLD);
            wmma::load_matrix_sync(b1, Bb + (kf * 16) * BLD + wn * 32 + 16, BLD);
            wmma::mma_sync(c[0][0], a0, b0, c[0][0]);
            wmma::mma_sync(c[0][1], a0, b1, c[0][1]);
            wmma::mma_sync(c[1][0], a1, b0, c[1][0]);
            wmma::mma_sync(c[1][1], a1, b1, c[1][1]);
        }
        loadStage(it + 3);
    }

    // ---- epilogue: accumulators -> smem(fp32) -> elementwise ----
    __syncthreads();
    float* E = reinterpret_cast<float*>(smem);   // [64][72] fp32 = 18432 B
    #pragma unroll
    for (int i = 0; i < 2; i++)
        #pragma unroll
        for (int j = 0; j < 2; j++)
            wmma::store_matrix_sync(E + (size_t)(wm * 32 + i * 16) * BLD + wn * 32 + j * 16,
                                    c[i][j], BLD, wmma::mem_row_major);
    __syncthreads();

    const int r     = tid >> 1;           // 0..63
    const int cbase = (tid & 1) * 32;     // 0 / 32

    if (MODE == 0) {
        #pragma unroll
        for (int j = 0; j < 8; j++) {
            int col = cbase + j * 4;
            float4 v = *reinterpret_cast<float4*>(&E[r * BLD + col]);
            __half h0 = __float2half_rn(tanhf(v.x + bias[bn + col + 0]));
            __half h1 = __float2half_rn(tanhf(v.y + bias[bn + col + 1]));
            __half h2 = __float2half_rn(tanhf(v.z + bias[bn + col + 2]));
            __half h3 = __float2half_rn(tanhf(v.w + bias[bn + col + 3]));
            __half2 p0 = __halves2half2(h0, h1);
            __half2 p1 = __halves2half2(h2, h3);
            uint2 pk = make_uint2(*reinterpret_cast<uint32_t*>(&p0),
                                  *reinterpret_cast<uint32_t*>(&p1));
            *reinterpret_cast<uint2*>(&Cout[(size_t)(bm + r) * N + bn + col]) = pk;
        }
    } else {
        const float dt = ts[t + 1] - ts[t];
        #pragma unroll
        for (int j = 0; j < 8; j++) {
            int col = cbase + j * 4;
            int idx = (bm + r) * X_ + bn + col;
            float4 yv = *reinterpret_cast<float4*>(&gy[idx]);
            yv.x += dt * (E[r * BLD + col + 0] + bias[bn + col + 0]);
            yv.y += dt * (E[r * BLD + col + 1] + bias[bn + col + 1]);
            yv.z += dt * (E[r * BLD + col + 2] + bias[bn + col + 2]);
            yv.w += dt * (E[r * BLD + col + 3] + bias[bn + col + 3]);
            *reinterpret_cast<float4*>(&gy[idx]) = yv;
            __half2 p0 = __halves2half2(__float2half_rn(yv.x), __float2half_rn(yv.y));
            __half2 p1 = __halves2half2(__float2half_rn(yv.z), __float2half_rn(yv.w));
            uint2 pk = make_uint2(*reinterpret_cast<uint32_t*>(&p0),
                                  *reinterpret_cast<uint32_t*>(&p1));
            *reinterpret_cast<uint2*>(&gyh[idx]) = pk;
            *reinterpret_cast<float4*>(&out[(size_t)(bm + r) * T_ * X_ +
                                            (size_t)(t + 1) * X_ + bn + col]) = yv;
        }
    }
}

// ---------------- host ----------------
extern "C" void kernel_launch(void* const* d_in, const int* in_sizes, int n_in,
                              void* d_out, int out_size)
{
    const float* x     = (const float*)d_in[0];
    const float* ts    = (const float*)d_in[1];
    const float* W_in  = (const float*)d_in[2];
    const float* b_in  = (const float*)d_in[3];
    const float* W_h   = (const float*)d_in[4];
    const float* b_h   = (const float*)d_in[5];
    const float* W_out = (const float*)d_in[6];
    const float* b_out = (const float*)d_in[7];
    float* out = (float*)d_out;

    float  *py;
    __half *pyh, *ph0, *ph1, *pwh;
    cudaGetSymbolAddress((void**)&py,  g_y);
    cudaGetSymbolAddress((void**)&pyh, g_yh);
    cudaGetSymbolAddress((void**)&ph0, g_h0);
    cudaGetSymbolAddress((void**)&ph1, g_h1);
    cudaGetSymbolAddress((void**)&pwh, g_wh);

    cudaFuncSetAttribute(gemm_wmma<0>, cudaFuncAttributeMaxDynamicSharedMemorySize, DYN_SMEM);
    cudaFuncSetAttribute(gemm_wmma<1>, cudaFuncAttributeMaxDynamicSharedMemorySize, DYN_SMEM);

    cvt_kernel<<<(X_ * H_ + 255) / 256, 256>>>(W_in,  pwh + WH_IN_OFF,  X_ * H_);
    cvt_kernel<<<(3 * H_ * H_ + 255) / 256, 256>>>(W_h, pwh + WH_H_OFF, 3 * H_ * H_);
    cvt_kernel<<<(H_ * X_ + 255) / 256, 256>>>(W_out, pwh + WH_OUT_OFF, H_ * X_);

    node_init_kernel<<<(B_ * X_) / 256, 256>>>(x, out);

    dim3 blk(128);
    dim3 gridH(H_ / BN, B_ / BM);   // (16, 4) = 64 CTAs
    dim3 gridO(X_ / BN, B_ / BM);   // (4, 4)  = 16 CTAs

    const __half* Wh_in  = pwh + WH_IN_OFF;
    const __half* Wh_h   = pwh + WH_H_OFF;
    const __half* Wh_out = pwh + WH_OUT_OFF;

    for (int t = 0; t < T_ - 1; t++) {
        gemm_wmma<0><<<gridH, blk, DYN_SMEM>>>(pyh, Wh_in,          b_in,       ph0, X_, H_, nullptr, nullptr, nullptr, nullptr, 0);
        gemm_wmma<0><<<gridH, blk, DYN_SMEM>>>(ph0, Wh_h + 0*H_*H_, b_h + 0*H_, ph1, H_, H_, nullptr, nullptr, nullptr, nullptr, 0);
        gemm_wmma<0><<<gridH, blk, DYN_SMEM>>>(ph1, Wh_h + 1*H_*H_, b_h + 1*H_, ph0, H_, H_, nullptr, nullptr, nullptr, nullptr, 0);
        gemm_wmma<0><<<gridH, blk, DYN_SMEM>>>(ph0, Wh_h + 2*H_*H_, b_h + 2*H_, ph1, H_, H_, nullptr, nullptr, nullptr, nullptr, 0);
        gemm_wmma<1><<<gridO, blk, DYN_SMEM>>>(ph1, Wh_out,         b_out, nullptr, H_, X_, py, pyh, out, ts, t);
    }
}